// round 2
// baseline (speedup 1.0000x reference)
#include <cuda_runtime.h>

#define NN 100000
#define DEG 8
#define HD 128
#define H3 384

typedef unsigned long long u64;

__device__ __forceinline__ u64 pk2(float lo, float hi){u64 r;asm("mov.b64 %0,{%1,%2};":"=l"(r):"f"(lo),"f"(hi));return r;}
__device__ __forceinline__ u64 bc2(float a){u64 r;asm("mov.b64 %0,{%1,%1};":"=l"(r):"f"(a));return r;}
__device__ __forceinline__ void upk2(u64 v,float&lo,float&hi){asm("mov.b64 {%0,%1},%2;":"=f"(lo),"=f"(hi):"l"(v));}
__device__ __forceinline__ u64 fma2(u64 a,u64 b,u64 c){u64 d;asm("fma.rn.f32x2 %0,%1,%2,%3;":"=l"(d):"l"(a),"l"(b),"l"(c));return d;}

__device__ __forceinline__ float sigf(float x){return __fdividef(1.0f,1.0f+__expf(-x));}
__device__ __forceinline__ float tanhf_(float x){return 2.0f*sigf(2.0f*x)-1.0f;}
__device__ __forceinline__ float g2(const float2&v,int k){return k==0?v.x:v.y;}
__device__ __forceinline__ float g4(const float4&v,int k){return k==0?v.x:(k==1?v.y:(k==2?v.z:v.w));}

// ---------------- Kernel 1: forget path -> c_aggr (scratch in c half of d_out)
// 64 nodes/CTA, 256 thr; thread tile 8 nodes x 4 feats. smem: h[64][128]+U_f[128][128]=96KB.
__global__ __launch_bounds__(256,2)
void k_forget(const float* __restrict__ nh,const float* __restrict__ nc,
              const float* __restrict__ f_in,const float* __restrict__ U_f,
              const float* __restrict__ b_f,float* __restrict__ c_aggr)
{
    extern __shared__ float sm[];
    float* h_s=sm;            // [64][128]
    float* u_s=sm+64*HD;      // [128][128]
    const int tid=threadIdx.x, node0=blockIdx.x*64;
    const int fg=tid&31, ng=tid>>5, f0=fg*4;

    float cacc[8][4];
#pragma unroll
    for(int i=0;i<8;i++){cacc[i][0]=cacc[i][1]=cacc[i][2]=cacc[i][3]=0.f;}

    for(int d=0;d<DEG;d++){
        __syncthreads();
#pragma unroll
        for(int r=0;r<8;r++){
            int idx=tid+r*256, n=idx>>5, k4=idx&31, gn=node0+n;
            float4 v=make_float4(0.f,0.f,0.f,0.f);
            if(gn<NN) v=*reinterpret_cast<const float4*>(nh+((size_t)gn*DEG+d)*HD+k4*4);
            *reinterpret_cast<float4*>(h_s+n*HD+k4*4)=v;
        }
        {
            const float4* ug=reinterpret_cast<const float4*>(U_f+(size_t)d*HD*HD);
            float4* us=reinterpret_cast<float4*>(u_s);
#pragma unroll
            for(int r=0;r<16;r++) us[tid+r*256]=ug[tid+r*256];
        }
        __syncthreads();

        u64 fp[8][2];
        {
            float4 bf=*reinterpret_cast<const float4*>(b_f+d*HD+f0);
            u64 lo=pk2(bf.x,bf.y),hi=pk2(bf.z,bf.w);
#pragma unroll
            for(int i=0;i<8;i++){fp[i][0]=lo;fp[i][1]=hi;}
        }
#pragma unroll 1
        for(int k=0;k<HD;k+=2){
            float2 a2[8];
#pragma unroll
            for(int i=0;i<8;i++) a2[i]=*reinterpret_cast<const float2*>(h_s+(ng*8+i)*HD+k);
#pragma unroll
            for(int kk=0;kk<2;kk++){
                float4 b4=*reinterpret_cast<const float4*>(u_s+(k+kk)*HD+f0);
                u64 bl=pk2(b4.x,b4.y),bh=pk2(b4.z,b4.w);
#pragma unroll
                for(int i=0;i<8;i++){
                    u64 a=bc2(g2(a2[i],kk));
                    fp[i][0]=fma2(a,bl,fp[i][0]);
                    fp[i][1]=fma2(a,bh,fp[i][1]);
                }
            }
        }
#pragma unroll
        for(int i=0;i<8;i++){
            int gn=node0+ng*8+i;
            if(gn<NN){
                float4 fi=*reinterpret_cast<const float4*>(f_in+(size_t)gn*HD+f0);
                float4 cv=*reinterpret_cast<const float4*>(nc+((size_t)gn*DEG+d)*HD+f0);
                float p0,p1,p2,p3; upk2(fp[i][0],p0,p1); upk2(fp[i][1],p2,p3);
                cacc[i][0]+=sigf(p0+fi.x)*cv.x;
                cacc[i][1]+=sigf(p1+fi.y)*cv.y;
                cacc[i][2]+=sigf(p2+fi.z)*cv.z;
                cacc[i][3]+=sigf(p3+fi.w)*cv.w;
            }
        }
    }
#pragma unroll
    for(int i=0;i<8;i++){
        int gn=node0+ng*8+i;
        if(gn<NN)
            *reinterpret_cast<float4*>(c_aggr+(size_t)gn*HD+f0)=
                make_float4(cacc[i][0],cacc[i][1],cacc[i][2],cacc[i][3]);
    }
}

// ---------------- Kernel 2: iou GEMM [N,1024]x[1024,384] + finalize h,c.
// 32 nodes/CTA (3125 blocks exact), 256 thr; thread tile 4 nodes x 12 feats.
// smem: A[32][128] (16KB) + B[32][384] (48KB, reused as iou staging).
__global__ __launch_bounds__(256,2)
void k_iou(const float* __restrict__ nh,const float* __restrict__ iou_in,
           const float* __restrict__ U_a,const float* __restrict__ b_a,
           float* __restrict__ h_out,float* __restrict__ c_io)
{
    extern __shared__ float sm[];
    float* a_s=sm;            // [32][128]
    float* b_s=sm+32*HD;      // [32][384]
    const int tid=threadIdx.x, node0=blockIdx.x*32;
    const int fg=tid&31, ng=tid>>5, f0=fg*12;

    u64 acc[4][6];
#pragma unroll
    for(int i=0;i<4;i++)
#pragma unroll
        for(int j=0;j<6;j++) acc[i][j]=0ull;

    for(int d=0;d<DEG;d++){
        __syncthreads();
#pragma unroll
        for(int r=0;r<4;r++){
            int idx=tid+r*256, n=idx>>5, k4=idx&31;
            *reinterpret_cast<float4*>(a_s+n*HD+k4*4)=
                *reinterpret_cast<const float4*>(nh+((size_t)(node0+n)*DEG+d)*HD+k4*4);
        }
        for(int kb=0;kb<4;kb++){
            __syncthreads();
#pragma unroll
            for(int r=0;r<12;r++){
                int idx=tid+r*256, kk=idx/96, fq=idx%96;
                *reinterpret_cast<float4*>(b_s+kk*H3+fq*4)=
                    *reinterpret_cast<const float4*>(U_a+((size_t)(d*HD+kb*32+kk))*H3+fq*4);
            }
            __syncthreads();
#pragma unroll 1
            for(int k=0;k<32;k+=4){
                float4 a4[4];
#pragma unroll
                for(int i=0;i<4;i++)
                    a4[i]=*reinterpret_cast<const float4*>(a_s+(ng*4+i)*HD+kb*32+k);
#pragma unroll
                for(int kk=0;kk<4;kk++){
                    const float* br=b_s+(k+kk)*H3+f0;
                    float4 b0=*reinterpret_cast<const float4*>(br);
                    float4 b1=*reinterpret_cast<const float4*>(br+4);
                    float4 b2=*reinterpret_cast<const float4*>(br+8);
                    u64 p0=pk2(b0.x,b0.y),p1=pk2(b0.z,b0.w);
                    u64 p2=pk2(b1.x,b1.y),p3=pk2(b1.z,b1.w);
                    u64 p4=pk2(b2.x,b2.y),p5=pk2(b2.z,b2.w);
#pragma unroll
                    for(int i=0;i<4;i++){
                        u64 a=bc2(g4(a4[i],kk));
                        acc[i][0]=fma2(a,p0,acc[i][0]);
                        acc[i][1]=fma2(a,p1,acc[i][1]);
                        acc[i][2]=fma2(a,p2,acc[i][2]);
                        acc[i][3]=fma2(a,p3,acc[i][3]);
                        acc[i][4]=fma2(a,p4,acc[i][4]);
                        acc[i][5]=fma2(a,p5,acc[i][5]);
                    }
                }
            }
        }
    }

    __syncthreads();
    {   // stage iou_aggr + b_aggr into b_s so i/o/u can be regrouped per node
        float4 a0=*reinterpret_cast<const float4*>(b_a+f0);
        float4 a1=*reinterpret_cast<const float4*>(b_a+f0+4);
        float4 a2=*reinterpret_cast<const float4*>(b_a+f0+8);
#pragma unroll
        for(int i=0;i<4;i++){
            float v[12];
            upk2(acc[i][0],v[0],v[1]); upk2(acc[i][1],v[2],v[3]);
            upk2(acc[i][2],v[4],v[5]); upk2(acc[i][3],v[6],v[7]);
            upk2(acc[i][4],v[8],v[9]); upk2(acc[i][5],v[10],v[11]);
            v[0]+=a0.x;v[1]+=a0.y;v[2]+=a0.z;v[3]+=a0.w;
            v[4]+=a1.x;v[5]+=a1.y;v[6]+=a1.z;v[7]+=a1.w;
            v[8]+=a2.x;v[9]+=a2.y;v[10]+=a2.z;v[11]+=a2.w;
            float* row=b_s+(ng*4+i)*H3+f0;
            *reinterpret_cast<float4*>(row)  =make_float4(v[0],v[1],v[2],v[3]);
            *reinterpret_cast<float4*>(row+4)=make_float4(v[4],v[5],v[6],v[7]);
            *reinterpret_cast<float4*>(row+8)=make_float4(v[8],v[9],v[10],v[11]);
        }
    }
    __syncthreads();
    {   // finalize: 1 node x 16 feats per thread
        const int nn=tid>>3, fb=(tid&7)*16, gn=node0+nn;
        const float* ios=b_s+nn*H3;
        const float* iin=iou_in+(size_t)gn*H3;
#pragma unroll
        for(int j=0;j<16;j+=4){
            int f=fb+j;
            float4 vi=*reinterpret_cast<const float4*>(ios+f);
            float4 vo=*reinterpret_cast<const float4*>(ios+f+128);
            float4 vu=*reinterpret_cast<const float4*>(ios+f+256);
            float4 ii=*reinterpret_cast<const float4*>(iin+f);
            float4 io=*reinterpret_cast<const float4*>(iin+f+128);
            float4 iu=*reinterpret_cast<const float4*>(iin+f+256);
            float4 ca=*reinterpret_cast<const float4*>(c_io+(size_t)gn*HD+f);
            float4 cR,hR;
            cR.x=sigf(vi.x+ii.x)*tanhf_(vu.x+iu.x)+ca.x;
            cR.y=sigf(vi.y+ii.y)*tanhf_(vu.y+iu.y)+ca.y;
            cR.z=sigf(vi.z+ii.z)*tanhf_(vu.z+iu.z)+ca.z;
            cR.w=sigf(vi.w+ii.w)*tanhf_(vu.w+iu.w)+ca.w;
            hR.x=sigf(vo.x+io.x)*tanhf_(cR.x);
            hR.y=sigf(vo.y+io.y)*tanhf_(cR.y);
            hR.z=sigf(vo.z+io.z)*tanhf_(cR.z);
            hR.w=sigf(vo.w+io.w)*tanhf_(cR.w);
            *reinterpret_cast<float4*>(h_out+(size_t)gn*HD+f)=hR;
            *reinterpret_cast<float4*>(c_io +(size_t)gn*HD+f)=cR;
        }
    }
}

extern "C" void kernel_launch(void* const* d_in, const int* in_sizes, int n_in,
                              void* d_out, int out_size)
{
    const float* nh    =(const float*)d_in[0];
    const float* nc    =(const float*)d_in[1];
    const float* f_in  =(const float*)d_in[2];
    const float* iou_in=(const float*)d_in[3];
    const float* U_f   =(const float*)d_in[4];
    const float* b_f   =(const float*)d_in[5];
    const float* U_a   =(const float*)d_in[6];
    const float* b_a   =(const float*)d_in[7];

    float* h_out=(float*)d_out;
    float* c_out=h_out+(size_t)NN*HD;

    const int smem1=(64*HD+HD*HD)*(int)sizeof(float);  // 96 KB
    const int smem2=(32*HD+32*H3)*(int)sizeof(float);  // 64 KB
    static bool attr_done=false;
    if(!attr_done){
        cudaFuncSetAttribute(k_forget,cudaFuncAttributeMaxDynamicSharedMemorySize,smem1);
        cudaFuncSetAttribute(k_iou,   cudaFuncAttributeMaxDynamicSharedMemorySize,smem2);
        attr_done=true;
    }

    k_forget<<<(NN+63)/64,256,smem1>>>(nh,nc,f_in,U_f,b_f,c_out);
    k_iou<<<NN/32,256,smem2>>>(nh,iou_in,U_a,b_a,h_out,c_out);
}